// round 13
// baseline (speedup 1.0000x reference)
#include <cuda_runtime.h>
#include <cuda_bf16.h>
#include <math.h>
#include <stdint.h>

#define BB   128
#define SSQ  512
#define EE   300
#define KP0  320
#define HH   256
#define FH   1024
#define TT   9
#define VV   50000
#define MTOT (BB*SSQ)

// ---------------- static device scratch ----------------
__device__ float g_gA[(size_t)MTOT * FH];
__device__ float g_gB[(size_t)MTOT * FH];
__device__ float g_l1[(size_t)MTOT * 2 * HH];
__device__ __nv_bfloat16 g_hh[2][2][BB * HH];   // h hi  [parity][dir][b][k]
__device__ __nv_bfloat16 g_hl[2][2][BB * HH];   // h lo
__device__ float g_em[(size_t)MTOT * TT];
__device__ float g_part[BB];
__device__ unsigned g_cnt[2];
__device__ unsigned g_gen[2];

// bf16 split buffers
__device__ __nv_bfloat16 g_embh[(size_t)VV * KP0];
__device__ __nv_bfloat16 g_embl[(size_t)VV * KP0];
__device__ __nv_bfloat16 g_Wh[4][(size_t)FH * 512];
__device__ __nv_bfloat16 g_Wl[4][(size_t)FH * 512];
__device__ __nv_bfloat16 g_l0h[(size_t)MTOT * 512];
__device__ __nv_bfloat16 g_l0l[(size_t)MTOT * 512];

// ---------------- helpers ----------------
__device__ __forceinline__ uint32_t smem_u32(const void* p) {
    uint32_t a;
    asm("{ .reg .u64 t; cvta.to.shared.u64 t, %1; cvt.u32.u64 %0, t; }" : "=r"(a) : "l"(p));
    return a;
}
__device__ __forceinline__ void cpa16(uint32_t dst, const void* src) {
    asm volatile("cp.async.cg.shared.global [%0], [%1], 16;" :: "r"(dst), "l"(src));
}
__device__ __forceinline__ void ldmat4(uint32_t& r0, uint32_t& r1, uint32_t& r2, uint32_t& r3,
                                       uint32_t addr) {
    asm volatile("ldmatrix.sync.aligned.m8n8.x4.shared.b16 {%0,%1,%2,%3}, [%4];"
                 : "=r"(r0), "=r"(r1), "=r"(r2), "=r"(r3) : "r"(addr));
}
__device__ __forceinline__ void mma_bf16(float* d, const uint32_t* a, const uint32_t* b) {
    asm volatile(
        "mma.sync.aligned.m16n8k16.row.col.f32.bf16.bf16.f32 "
        "{%0,%1,%2,%3}, {%4,%5,%6,%7}, {%8,%9}, {%0,%1,%2,%3};"
        : "+f"(d[0]), "+f"(d[1]), "+f"(d[2]), "+f"(d[3])
        : "r"(a[0]), "r"(a[1]), "r"(a[2]), "r"(a[3]), "r"(b[0]), "r"(b[1]));
}
__device__ __forceinline__ unsigned ld_acq(const unsigned* p) {
    unsigned v;
    asm volatile("ld.acquire.gpu.global.u32 %0, [%1];" : "=r"(v) : "l"(p) : "memory");
    return v;
}
__device__ __forceinline__ unsigned atom_add_acqrel(unsigned* p, unsigned v) {
    unsigned old;
    asm volatile("atom.acq_rel.gpu.global.add.u32 %0, [%1], %2;"
                 : "=r"(old) : "l"(p), "r"(v) : "memory");
    return old;
}
__device__ __forceinline__ void red_add_release(unsigned* p, unsigned v) {
    asm volatile("red.release.gpu.global.add.u32 [%0], %1;" :: "l"(p), "r"(v) : "memory");
}

// ---------------- split conversion: fp32 -> bf16 hi/lo, padded ----------------
__global__ void __launch_bounds__(256)
split_rows_kernel(const float* __restrict__ src, __nv_bfloat16* __restrict__ hi,
                  __nv_bfloat16* __restrict__ lo, int K, int Kpad)
{
    const long r = blockIdx.x;
    const float* s = src + r * (long)K;
    __nv_bfloat16* hh = hi + r * (long)Kpad;
    __nv_bfloat16* ll = lo + r * (long)Kpad;
    for (int c = threadIdx.x; c < Kpad; c += blockDim.x) {
        float v = (c < K) ? s[c] : 0.f;
        __nv_bfloat16 h = __float2bfloat16(v);
        float res = v - __bfloat162float(h);
        hh[c] = h;
        ll[c] = __float2bfloat16(res);
    }
}

// ---------------- mma.sync bf16 split GEMM (proven R9) ----------------
#define GSTG      3
#define GROWB     80
#define GARR      (128 * GROWB)
#define GSTAGEB   (4 * GARR)
#define GEMM_SMEM (GSTG * GSTAGEB)

__global__ void __launch_bounds__(256)
mma_gemm_kernel(const __nv_bfloat16* __restrict__ Ahi, const __nv_bfloat16* __restrict__ Alo,
                const __nv_bfloat16* __restrict__ Whi, const __nv_bfloat16* __restrict__ Wlo,
                const float* __restrict__ bias, float* __restrict__ C,
                int Kpad, const int* __restrict__ rowidx)
{
    extern __shared__ __align__(16) char gsm[];
    __shared__ int xrow[128];

    const int tid = threadIdx.x;
    const int wid = tid >> 5;
    const int lane = tid & 31;
    const int m0 = blockIdx.x * 128;
    const int n0 = blockIdx.y * 128;
    const int wm = wid >> 2;
    const int wn = wid & 3;

    if (rowidx && tid < 128) xrow[tid] = rowidx[m0 + tid];
    __syncthreads();

    const uint32_t smb = smem_u32(gsm);
    const int nch = Kpad >> 5;

    const int lr_lo = tid >> 2;
    const int lks   = tid & 3;

    auto load_stage = [&](int c, int buf) {
        const uint32_t sb = smb + buf * GSTAGEB;
#pragma unroll
        for (int j = 0; j < 8; j++) {
            const int part = j >> 1;
            const int r    = (j & 1) * 64 + lr_lo;
            const uint32_t dst = sb + part * GARR + r * GROWB + lks * 16;
            const __nv_bfloat16* base;
            long row;
            if (part < 2) {
                base = (part == 0) ? Ahi : Alo;
                row  = rowidx ? xrow[r] : (m0 + r);
            } else {
                base = (part == 2) ? Whi : Wlo;
                row  = n0 + r;
            }
            cpa16(dst, base + row * (long)Kpad + c * 32 + lks * 8);
        }
        asm volatile("cp.async.commit_group;" ::: "memory");
    };

    float acc[4][4][4];
#pragma unroll
    for (int i = 0; i < 4; i++)
#pragma unroll
        for (int j = 0; j < 4; j++)
#pragma unroll
            for (int k = 0; k < 4; k++) acc[i][j][k] = 0.f;

    load_stage(0, 0);
    load_stage(1, 1);

    for (int c = 0; c < nch; c++) {
        if (c + 2 < nch) load_stage(c + 2, (c + 2) % GSTG);
        else asm volatile("cp.async.commit_group;" ::: "memory");
        asm volatile("cp.async.wait_group 2;" ::: "memory");
        __syncthreads();

        const uint32_t sb = smb + (c % GSTG) * GSTAGEB;
        const uint32_t aHb = sb;
        const uint32_t aLb = sb + GARR;
        const uint32_t bHb = sb + 2 * GARR;
        const uint32_t bLb = sb + 3 * GARR;

        const int a_row = (lane & 7) + ((lane >> 3) & 1) * 8;
        const int a_kb  = (lane >> 4) * 16;
        const int b_row = (lane & 7) + (lane >> 4) * 8;
        const int b_kb  = ((lane >> 3) & 1) * 16;

#pragma unroll
        for (int ks = 0; ks < 2; ks++) {
            const int kb = ks * 32;
            uint32_t ah[4][4], al[4][4], bh[2][4], bl[2][4];
#pragma unroll
            for (int mt = 0; mt < 4; mt++) {
                const uint32_t off = (wm * 64 + mt * 16 + a_row) * GROWB + kb + a_kb;
                ldmat4(ah[mt][0], ah[mt][1], ah[mt][2], ah[mt][3], aHb + off);
                ldmat4(al[mt][0], al[mt][1], al[mt][2], al[mt][3], aLb + off);
            }
#pragma unroll
            for (int np = 0; np < 2; np++) {
                const uint32_t off = (wn * 32 + np * 16 + b_row) * GROWB + kb + b_kb;
                ldmat4(bh[np][0], bh[np][1], bh[np][2], bh[np][3], bHb + off);
                ldmat4(bl[np][0], bl[np][1], bl[np][2], bl[np][3], bLb + off);
            }
#pragma unroll
            for (int mt = 0; mt < 4; mt++) {
#pragma unroll
                for (int nt = 0; nt < 4; nt++) {
                    uint32_t bfh[2] = { bh[nt >> 1][(nt & 1) * 2], bh[nt >> 1][(nt & 1) * 2 + 1] };
                    uint32_t bfl[2] = { bl[nt >> 1][(nt & 1) * 2], bl[nt >> 1][(nt & 1) * 2 + 1] };
                    mma_bf16(acc[mt][nt], ah[mt], bfh);
                    mma_bf16(acc[mt][nt], al[mt], bfh);
                    mma_bf16(acc[mt][nt], ah[mt], bfl);
                }
            }
        }
        __syncthreads();
    }

    const int g   = lane >> 2;
    const int t2  = (lane & 3) * 2;
#pragma unroll
    for (int mt = 0; mt < 4; mt++) {
        const int m = m0 + wm * 64 + mt * 16 + g;
#pragma unroll
        for (int nt = 0; nt < 4; nt++) {
            const int n = n0 + wn * 32 + nt * 8 + t2;
            const float b0 = bias[n], b1 = bias[n + 1];
            float2 v0 = make_float2(acc[mt][nt][0] + b0, acc[mt][nt][1] + b1);
            float2 v1 = make_float2(acc[mt][nt][2] + b0, acc[mt][nt][3] + b1);
            *(float2*)(C + (size_t)m * FH + n)       = v0;
            *(float2*)(C + (size_t)(m + 8) * FH + n) = v1;
        }
    }
}

// ---------------- LSTM scan: 64 blocks/dir x 4 units, TC matmul, in-warp combine ----------------
// smem (bytes): hsH 67584 | hsL 67584 | wsH 8448 | wsL 8448 | xst 8192
#define HSROWB   528
#define OFF_HSH  0
#define OFF_HSL  67584
#define OFF_WSH  135168
#define OFF_WSL  143616
#define OFF_XST  152064
#define SCAN_SMEM_BYTES (152064 + 8192)

__device__ __forceinline__ float sigm(float x) { return 1.0f / (1.0f + expf(-x)); }

__global__ void __launch_bounds__(256, 1)
lstm_scan_kernel(const float* __restrict__ xWf, const float* __restrict__ xWb,
                 const float* __restrict__ WhhF, const float* __restrict__ WhhB,
                 float* __restrict__ lout,
                 __nv_bfloat16* __restrict__ sph, __nv_bfloat16* __restrict__ spl)
{
    extern __shared__ __align__(16) char smem[];
    float* xst = (float*)(smem + OFF_XST);

    const int tid   = threadIdx.x;
    const int dir   = blockIdx.x >> 6;
    const int slice = blockIdx.x & 63;
    const int j0    = slice << 2;

    const float* xW  = dir ? xWb  : xWf;
    const float* Whh = dir ? WhhB : WhhF;

    const uint32_t smb = smem_u32(smem);

    // convert Whh slice -> ws hi/lo (bf16, [16][264] rows); row l = q*4+jj
    {
        const int l  = tid >> 4;
        const int ks = (tid & 15) * 16;
        const int grow = ((l >> 2) * HH) + j0 + (l & 3);
        const float* src = Whh + (size_t)grow * HH + ks;
        __nv_bfloat16* wh = (__nv_bfloat16*)(smem + OFF_WSH) + l * 264 + ks;
        __nv_bfloat16* wl = (__nv_bfloat16*)(smem + OFF_WSL) + l * 264 + ks;
#pragma unroll
        for (int i = 0; i < 16; i++) {
            float v = src[i];
            __nv_bfloat16 h = __float2bfloat16(v);
            wh[i] = h;
            wl[i] = __float2bfloat16(v - __bfloat162float(h));
        }
    }
    // zero hs (h0 = 0)
    {
        float4* d4 = (float4*)(smem);
        float4 z = make_float4(0,0,0,0);
        for (int i = tid; i < (2 * 67584) / 16; i += 256) d4[i] = z;
    }
    __syncthreads();

    const int w = tid >> 5;
    const int lane = tid & 31;
    const int g  = lane >> 2;
    const int t2 = (lane & 3) * 2;
    const int a_row = (lane & 7) + ((lane >> 3) & 1) * 8;
    const int a_kb  = (lane >> 4) * 16;
    const int b_row = (lane & 7) + (lane >> 4) * 8;
    const int b_kb  = ((lane >> 3) & 1) * 16;

    // in-warp combine ownership: lanes<16 take o=0 cols, lanes>=16 take o=1 cols; unit u = g&3
    const int u     = g & 3;
    const int o_sel = (lane < 16) ? 0 : 1;
    const int bcol  = w * 16 + o_sel * 8 + t2;   // first of 2 batch cols

    float creg[2] = {0.f, 0.f};                  // c-state for (bcol, u), (bcol+1, u)

    for (int tt = 0; tt < SSQ; tt++) {
        const int t = dir ? (SSQ - 1 - tt) : tt;

        // load h(t-1) bf16 hi/lo into smem ([b][k] rows, 528B stride)
        if (tt > 0) {
            const int par = (tt - 1) & 1;
            const float4* srcH = (const float4*)(g_hh[par][dir]);
            const float4* srcL = (const float4*)(g_hl[par][dir]);
#pragma unroll
            for (int i = 0; i < 16; i++) {
                const int seg = tid + i * 256;
                const int row = seg >> 5;
                const int s   = seg & 31;
                *(float4*)(smem + OFF_HSH + row * HSROWB + s * 16) = srcH[seg];
                *(float4*)(smem + OFF_HSL + row * HSROWB + s * 16) = srcL[seg];
            }
        }
        // stage xW slice: xst[q*4+c][b]
#pragma unroll
        for (int half = 0; half < 2; half++) {
            const int p = tid + (half << 8);
            const int q = p >> 7;
            const int b = p & 127;
            float4 v = *(const float4*)&xW[((size_t)b * SSQ + t) * FH + (q << 8) + j0];
            xst[((q<<2)+0)*128 + b] = v.x;
            xst[((q<<2)+1)*128 + b] = v.y;
            xst[((q<<2)+2)*128 + b] = v.z;
            xst[((q<<2)+3)*128 + b] = v.w;
        }
        __syncthreads();

        // ---- tensor-core recurrent matmul (in-register result) ----
        float acc[2][4];
#pragma unroll
        for (int o = 0; o < 2; o++)
#pragma unroll
            for (int k = 0; k < 4; k++) acc[o][k] = 0.f;

#pragma unroll 4
        for (int ck = 0; ck < 16; ck++) {
            const int kb = ck * 32;
            uint32_t ah[4], al[4], bh[4], bl[4];
            ldmat4(ah[0], ah[1], ah[2], ah[3], smb + OFF_WSH + a_row * HSROWB + kb + a_kb);
            ldmat4(al[0], al[1], al[2], al[3], smb + OFF_WSL + a_row * HSROWB + kb + a_kb);
            ldmat4(bh[0], bh[1], bh[2], bh[3],
                   smb + OFF_HSH + (w * 16 + b_row) * HSROWB + kb + b_kb);
            ldmat4(bl[0], bl[1], bl[2], bl[3],
                   smb + OFF_HSL + (w * 16 + b_row) * HSROWB + kb + b_kb);
#pragma unroll
            for (int o = 0; o < 2; o++) {
                uint32_t bfh[2] = { bh[o * 2], bh[o * 2 + 1] };
                uint32_t bfl[2] = { bl[o * 2], bl[o * 2 + 1] };
                mma_bf16(acc[o], ah, bfh);   // hi*hi
                mma_bf16(acc[o], al, bfh);   // lo*hi
                mma_bf16(acc[o], ah, bfl);   // hi*lo
            }
        }

        // ---- in-warp gate exchange: lanes L and L^16 hold complementary gate rows ----
        // own rows: g (acc[o][0..1]) and g+8 (acc[o][2..3]); partner rows: g^4 variants
        float pA[2][2], pB[2][2];
#pragma unroll
        for (int o = 0; o < 2; o++) {
            pA[o][0] = __shfl_xor_sync(0xffffffffu, acc[o][0], 16);
            pA[o][1] = __shfl_xor_sync(0xffffffffu, acc[o][1], 16);
            pB[o][0] = __shfl_xor_sync(0xffffffffu, acc[o][2], 16);
            pB[o][1] = __shfl_xor_sync(0xffffffffu, acc[o][3], 16);
        }

        // gates for this lane's cells (o_sel slot): rows i=u, f=4+u, gg=8+u, oo=12+u
        float giv[2], gfv[2], ggv[2], gov[2];
        if (lane < 16) {
            giv[0] = acc[o_sel][0]; giv[1] = acc[o_sel][1];     // row g   = i_u
            ggv[0] = acc[o_sel][2]; ggv[1] = acc[o_sel][3];     // row g+8 = gg_u
            gfv[0] = pA[o_sel][0];  gfv[1] = pA[o_sel][1];      // partner row g+4  = f_u
            gov[0] = pB[o_sel][0];  gov[1] = pB[o_sel][1];      // partner row g+12 = o_u
        } else {
            gfv[0] = acc[o_sel][0]; gfv[1] = acc[o_sel][1];     // row g (4..7)  = f_u
            gov[0] = acc[o_sel][2]; gov[1] = acc[o_sel][3];     // row g+8       = o_u
            giv[0] = pA[o_sel][0];  giv[1] = pA[o_sel][1];      // partner row g-4 = i_u
            ggv[0] = pB[o_sel][0];  ggv[1] = pB[o_sel][1];      // partner row g+4 = gg_u
        }

        // ---- gate combine (2 cells per lane) ----
        {
            const int par = tt & 1;
#pragma unroll
            for (int c2 = 0; c2 < 2; c2++) {
                const int b = bcol + c2;
                float gi = giv[c2] + xst[(0  + u)*128 + b];
                float gf = gfv[c2] + xst[(4  + u)*128 + b];
                float gg = ggv[c2] + xst[(8  + u)*128 + b];
                float go = gov[c2] + xst[(12 + u)*128 + b];
                float c  = creg[c2];
                float si = sigm(gi), sf = sigm(gf), so = sigm(go);
                c = sf * c + si * tanhf(gg);
                float h = so * tanhf(c);
                creg[c2] = c;
                __nv_bfloat16 hb = __float2bfloat16(h);
                g_hh[par][dir][b * HH + j0 + u] = hb;
                g_hl[par][dir][b * HH + j0 + u] = __float2bfloat16(h - __bfloat162float(hb));
                if (lout)
                    lout[((size_t)b * SSQ + t) * (2*HH) + dir*HH + j0 + u] = h;
                if (sph) {
                    const size_t off = ((size_t)b * SSQ + t) * (2*HH) + dir*HH + j0 + u;
                    __nv_bfloat16 s = __float2bfloat16(h);
                    sph[off] = s;
                    spl[off] = __float2bfloat16(h - __bfloat162float(s));
                }
            }
        }
        __syncthreads();

        // ---- per-direction grid barrier: release/acquire, tid0 only ----
        if (tt < SSQ - 1) {
            if (tid == 0) {
                unsigned gen = ld_acq(&g_gen[dir]);
                if (atom_add_acqrel(&g_cnt[dir], 1u) == 63u) {
                    g_cnt[dir] = 0u;
                    red_add_release(&g_gen[dir], 1u);
                } else {
                    while (ld_acq(&g_gen[dir]) == gen) __nanosleep(32);
                }
            }
            __syncthreads();
        }
    }
}

// ---------------- FC (T=9) ----------------
__global__ void __launch_bounds__(256)
fc_kernel(const float* __restrict__ l1, const float* __restrict__ fcw,
          const float* __restrict__ fcb, float* __restrict__ em)
{
    __shared__ float wsm[TT * 512];
    __shared__ float wb[TT];
    const int tid = threadIdx.x;
    for (int i = tid; i < TT*512; i += 256) wsm[i] = fcw[i];
    if (tid < TT) wb[tid] = fcb[tid];
    __syncthreads();

    const int warp = tid >> 5, lane = tid & 31;
    const int m = blockIdx.x * 8 + warp;
    const float* arow = l1 + (size_t)m * 512;
    float a[16];
#pragma unroll
    for (int c = 0; c < 16; c++) a[c] = arow[c*32 + lane];
    float* emrow = em + (size_t)m * TT;
#pragma unroll
    for (int j = 0; j < TT; j++) {
        float s = 0.f;
#pragma unroll
        for (int c = 0; c < 16; c++) s += a[c] * wsm[j*512 + c*32 + lane];
#pragma unroll
        for (int o = 16; o; o >>= 1) s += __shfl_xor_sync(0xffffffffu, s, o);
        if (lane == 0) emrow[j] = s + wb[j];
    }
}

// ---------------- CRF ----------------
__global__ void __launch_bounds__(1024)
crf_kernel(const int* __restrict__ x, const int* __restrict__ tags,
           const float* __restrict__ em, const float* __restrict__ start,
           const float* __restrict__ endv, const float* __restrict__ trans,
           float* __restrict__ partial)
{
    const int gw = (blockIdx.x * blockDim.x + threadIdx.x) >> 5;
    const int lane = threadIdx.x & 31;
    if (gw >= BB) return;
    const int b = gw;
    const float* emr = em + (size_t)b * SSQ * TT;
    const int* tg = tags + (size_t)b * SSQ;
    const int* xb = x + (size_t)b * SSQ;

    float nsum = 0.f; int mcount = 0;
    for (int s = lane; s < SSQ; s += 32) {
        const int m = (xb[s] != 0);
        mcount += m;
        if (s >= 1 && m) {
            const int tp = tg[s-1], tc = tg[s];
            nsum += trans[tp*TT + tc] + emr[(size_t)s*TT + tc];
        }
    }
#pragma unroll
    for (int o = 16; o; o >>= 1) {
        nsum   += __shfl_xor_sync(0xffffffffu, nsum, o);
        mcount += __shfl_xor_sync(0xffffffffu, mcount, o);
    }
    int last = mcount - 1; if (last < 0) last = 0;
    const int t0 = tg[0], tl = tg[last];
    const float num = nsum + start[t0] + emr[t0] + endv[tl];

    float tcol[TT];
#pragma unroll
    for (int i = 0; i < TT; i++) tcol[i] = 0.f;
    float alpha = -1e30f;
    if (lane < TT) {
#pragma unroll
        for (int i = 0; i < TT; i++) tcol[i] = trans[i*TT + lane];
        alpha = start[lane] + emr[lane];
    }
    for (int s = 1; s < SSQ; s++) {
        const float e = (lane < TT) ? emr[(size_t)s*TT + lane] : 0.f;
        const int m = (xb[s] != 0);
        float av[TT];
        float mx = -1e30f;
#pragma unroll
        for (int i = 0; i < TT; i++) {
            const float ai = __shfl_sync(0xffffffffu, alpha, i);
            av[i] = ai + tcol[i];
            mx = fmaxf(mx, av[i]);
        }
        float ssum = 0.f;
#pragma unroll
        for (int i = 0; i < TT; i++) ssum += expf(av[i] - mx);
        const float nxt = e + mx + logf(ssum);
        if (lane < TT && m) alpha = nxt;
    }
    float v = (lane < TT) ? alpha + endv[lane] : -1e30f;
    float mx = v;
#pragma unroll
    for (int o = 16; o; o >>= 1) mx = fmaxf(mx, __shfl_xor_sync(0xffffffffu, mx, o));
    float ex = (lane < TT) ? expf(v - mx) : 0.f;
#pragma unroll
    for (int o = 16; o; o >>= 1) ex += __shfl_xor_sync(0xffffffffu, ex, o);
    const float denom = mx + logf(ex);
    if (lane == 0) partial[b] = denom - num;
}

__global__ void reduce_mean_kernel(const float* __restrict__ partial, float* __restrict__ out)
{
    __shared__ float sm[BB];
    const int t = threadIdx.x;
    sm[t] = partial[t];
    __syncthreads();
    for (int o = 64; o; o >>= 1) { if (t < o) sm[t] += sm[t + o]; __syncthreads(); }
    if (t == 0) out[0] = sm[0] / (float)BB;
}

// ---------------- launch ----------------
extern "C" void kernel_launch(void* const* d_in, const int* in_sizes, int n_in,
                              void* d_out, int out_size)
{
    const int*   x     = (const int*)d_in[0];
    const int*   tags  = (const int*)d_in[1];
    const float* emb   = (const float*)d_in[2];
    const float* Wih0f = (const float*)d_in[3];
    const float* Whh0f = (const float*)d_in[4];
    const float* b0f   = (const float*)d_in[5];
    const float* Wih0b = (const float*)d_in[6];
    const float* Whh0b = (const float*)d_in[7];
    const float* b0b   = (const float*)d_in[8];
    const float* Wih1f = (const float*)d_in[9];
    const float* Whh1f = (const float*)d_in[10];
    const float* b1f   = (const float*)d_in[11];
    const float* Wih1b = (const float*)d_in[12];
    const float* Whh1b = (const float*)d_in[13];
    const float* b1b   = (const float*)d_in[14];
    const float* fcw   = (const float*)d_in[15];
    const float* fcb   = (const float*)d_in[16];
    const float* crf_s = (const float*)d_in[17];
    const float* crf_e = (const float*)d_in[18];
    const float* crf_t = (const float*)d_in[19];
    float* out = (float*)d_out;

    float *gA, *gB, *l1, *em, *part;
    cudaGetSymbolAddress((void**)&gA, g_gA);
    cudaGetSymbolAddress((void**)&gB, g_gB);
    cudaGetSymbolAddress((void**)&l1, g_l1);
    cudaGetSymbolAddress((void**)&em, g_em);
    cudaGetSymbolAddress((void**)&part, g_part);
    __nv_bfloat16 *embh, *embl, *Wh, *Wl, *l0h, *l0l;
    cudaGetSymbolAddress((void**)&embh, g_embh);
    cudaGetSymbolAddress((void**)&embl, g_embl);
    cudaGetSymbolAddress((void**)&Wh, g_Wh);
    cudaGetSymbolAddress((void**)&Wl, g_Wl);
    cudaGetSymbolAddress((void**)&l0h, g_l0h);
    cudaGetSymbolAddress((void**)&l0l, g_l0l);

    __nv_bfloat16* W0fh = Wh;                     __nv_bfloat16* W0fl = Wl;
    __nv_bfloat16* W0bh = Wh + (size_t)FH*512;    __nv_bfloat16* W0bl = Wl + (size_t)FH*512;
    __nv_bfloat16* W1fh = Wh + (size_t)FH*512*2;  __nv_bfloat16* W1fl = Wl + (size_t)FH*512*2;
    __nv_bfloat16* W1bh = Wh + (size_t)FH*512*3;  __nv_bfloat16* W1bl = Wl + (size_t)FH*512*3;

    cudaFuncSetAttribute(lstm_scan_kernel,
                         cudaFuncAttributeMaxDynamicSharedMemorySize, SCAN_SMEM_BYTES);
    cudaFuncSetAttribute(mma_gemm_kernel,
                         cudaFuncAttributeMaxDynamicSharedMemorySize, GEMM_SMEM);

    dim3 gg(MTOT/128, FH/128);

    // split conversions (weights + embedding; l0 split fused into scan)
    split_rows_kernel<<<VV, 256>>>(emb, embh, embl, EE, KP0);
    split_rows_kernel<<<FH, 256>>>(Wih0f, W0fh, W0fl, EE, KP0);
    split_rows_kernel<<<FH, 256>>>(Wih0b, W0bh, W0bl, EE, KP0);
    split_rows_kernel<<<FH, 256>>>(Wih1f, W1fh, W1fl, 512, 512);
    split_rows_kernel<<<FH, 256>>>(Wih1b, W1bh, W1bl, 512, 512);

    // layer 0
    mma_gemm_kernel<<<gg, 256, GEMM_SMEM>>>(embh, embl, W0fh, W0fl, b0f, gA, KP0, x);
    mma_gemm_kernel<<<gg, 256, GEMM_SMEM>>>(embh, embl, W0bh, W0bl, b0b, gB, KP0, x);
    lstm_scan_kernel<<<128, 256, SCAN_SMEM_BYTES>>>(gA, gB, Whh0f, Whh0b,
                                                    nullptr, l0h, l0l);
    // layer 1
    mma_gemm_kernel<<<gg, 256, GEMM_SMEM>>>(l0h, l0l, W1fh, W1fl, b1f, gA, 512, nullptr);
    mma_gemm_kernel<<<gg, 256, GEMM_SMEM>>>(l0h, l0l, W1bh, W1bl, b1b, gB, 512, nullptr);
    lstm_scan_kernel<<<128, 256, SCAN_SMEM_BYTES>>>(gA, gB, Whh1f, Whh1b,
                                                    l1, nullptr, nullptr);

    fc_kernel<<<MTOT/8, 256>>>(l1, fcw, fcb, em);
    crf_kernel<<<4, 1024>>>(x, tags, em, crf_s, crf_e, crf_t, part);
    reduce_mean_kernel<<<1, 128>>>(part, out);
}

// round 14
// speedup vs baseline: 1.5029x; 1.5029x over previous
#include <cuda_runtime.h>
#include <cuda_bf16.h>
#include <math.h>
#include <stdint.h>

#define BB   128
#define SSQ  512
#define EE   300
#define KP0  320
#define HH   256
#define FH   1024
#define TT   9
#define VV   50000
#define MTOT (BB*SSQ)

// ---------------- static device scratch ----------------
__device__ float g_gA[(size_t)MTOT * FH];
__device__ float g_gB[(size_t)MTOT * FH];
__device__ float g_l1[(size_t)MTOT * 2 * HH];
__device__ __nv_bfloat16 g_hh[2][2][BB * HH];   // h hi  [parity][dir][b][k]
__device__ __nv_bfloat16 g_hl[2][2][BB * HH];   // h lo
__device__ float g_em[(size_t)MTOT * TT];
__device__ float g_part[BB];
__device__ unsigned g_cnt[2];                    // monotonic barrier counters

// bf16 split buffers
__device__ __nv_bfloat16 g_embh[(size_t)VV * KP0];
__device__ __nv_bfloat16 g_embl[(size_t)VV * KP0];
__device__ __nv_bfloat16 g_Wh[4][(size_t)FH * 512];
__device__ __nv_bfloat16 g_Wl[4][(size_t)FH * 512];
__device__ __nv_bfloat16 g_l0h[(size_t)MTOT * 512];
__device__ __nv_bfloat16 g_l0l[(size_t)MTOT * 512];

// ---------------- helpers ----------------
__device__ __forceinline__ uint32_t smem_u32(const void* p) {
    uint32_t a;
    asm("{ .reg .u64 t; cvta.to.shared.u64 t, %1; cvt.u32.u64 %0, t; }" : "=r"(a) : "l"(p));
    return a;
}
__device__ __forceinline__ void cpa16(uint32_t dst, const void* src) {
    asm volatile("cp.async.cg.shared.global [%0], [%1], 16;" :: "r"(dst), "l"(src));
}
__device__ __forceinline__ void ldmat4(uint32_t& r0, uint32_t& r1, uint32_t& r2, uint32_t& r3,
                                       uint32_t addr) {
    asm volatile("ldmatrix.sync.aligned.m8n8.x4.shared.b16 {%0,%1,%2,%3}, [%4];"
                 : "=r"(r0), "=r"(r1), "=r"(r2), "=r"(r3) : "r"(addr));
}
__device__ __forceinline__ void mma_bf16(float* d, const uint32_t* a, const uint32_t* b) {
    asm volatile(
        "mma.sync.aligned.m16n8k16.row.col.f32.bf16.bf16.f32 "
        "{%0,%1,%2,%3}, {%4,%5,%6,%7}, {%8,%9}, {%0,%1,%2,%3};"
        : "+f"(d[0]), "+f"(d[1]), "+f"(d[2]), "+f"(d[3])
        : "r"(a[0]), "r"(a[1]), "r"(a[2]), "r"(a[3]), "r"(b[0]), "r"(b[1]));
}
__device__ __forceinline__ unsigned ld_acq(const unsigned* p) {
    unsigned v;
    asm volatile("ld.acquire.gpu.global.u32 %0, [%1];" : "=r"(v) : "l"(p) : "memory");
    return v;
}
__device__ __forceinline__ unsigned atom_add_acqrel(unsigned* p, unsigned v) {
    unsigned old;
    asm volatile("atom.acq_rel.gpu.global.add.u32 %0, [%1], %2;"
                 : "=r"(old) : "l"(p), "r"(v) : "memory");
    return old;
}

// ---------------- split conversion: fp32 -> bf16 hi/lo, padded ----------------
__global__ void __launch_bounds__(256)
split_rows_kernel(const float* __restrict__ src, __nv_bfloat16* __restrict__ hi,
                  __nv_bfloat16* __restrict__ lo, int K, int Kpad)
{
    const long r = blockIdx.x;
    const float* s = src + r * (long)K;
    __nv_bfloat16* hh = hi + r * (long)Kpad;
    __nv_bfloat16* ll = lo + r * (long)Kpad;
    for (int c = threadIdx.x; c < Kpad; c += blockDim.x) {
        float v = (c < K) ? s[c] : 0.f;
        __nv_bfloat16 h = __float2bfloat16(v);
        float res = v - __bfloat162float(h);
        hh[c] = h;
        ll[c] = __float2bfloat16(res);
    }
}

// ---------------- mma.sync bf16 split GEMM (proven R9) ----------------
#define GSTG      3
#define GROWB     80
#define GARR      (128 * GROWB)
#define GSTAGEB   (4 * GARR)
#define GEMM_SMEM (GSTG * GSTAGEB)

__global__ void __launch_bounds__(256)
mma_gemm_kernel(const __nv_bfloat16* __restrict__ Ahi, const __nv_bfloat16* __restrict__ Alo,
                const __nv_bfloat16* __restrict__ Whi, const __nv_bfloat16* __restrict__ Wlo,
                const float* __restrict__ bias, float* __restrict__ C,
                int Kpad, const int* __restrict__ rowidx)
{
    extern __shared__ __align__(16) char gsm[];
    __shared__ int xrow[128];

    const int tid = threadIdx.x;
    const int wid = tid >> 5;
    const int lane = tid & 31;
    const int m0 = blockIdx.x * 128;
    const int n0 = blockIdx.y * 128;
    const int wm = wid >> 2;
    const int wn = wid & 3;

    if (rowidx && tid < 128) xrow[tid] = rowidx[m0 + tid];
    __syncthreads();

    const uint32_t smb = smem_u32(gsm);
    const int nch = Kpad >> 5;

    const int lr_lo = tid >> 2;
    const int lks   = tid & 3;

    auto load_stage = [&](int c, int buf) {
        const uint32_t sb = smb + buf * GSTAGEB;
#pragma unroll
        for (int j = 0; j < 8; j++) {
            const int part = j >> 1;
            const int r    = (j & 1) * 64 + lr_lo;
            const uint32_t dst = sb + part * GARR + r * GROWB + lks * 16;
            const __nv_bfloat16* base;
            long row;
            if (part < 2) {
                base = (part == 0) ? Ahi : Alo;
                row  = rowidx ? xrow[r] : (m0 + r);
            } else {
                base = (part == 2) ? Whi : Wlo;
                row  = n0 + r;
            }
            cpa16(dst, base + row * (long)Kpad + c * 32 + lks * 8);
        }
        asm volatile("cp.async.commit_group;" ::: "memory");
    };

    float acc[4][4][4];
#pragma unroll
    for (int i = 0; i < 4; i++)
#pragma unroll
        for (int j = 0; j < 4; j++)
#pragma unroll
            for (int k = 0; k < 4; k++) acc[i][j][k] = 0.f;

    load_stage(0, 0);
    load_stage(1, 1);

    for (int c = 0; c < nch; c++) {
        if (c + 2 < nch) load_stage(c + 2, (c + 2) % GSTG);
        else asm volatile("cp.async.commit_group;" ::: "memory");
        asm volatile("cp.async.wait_group 2;" ::: "memory");
        __syncthreads();

        const uint32_t sb = smb + (c % GSTG) * GSTAGEB;
        const uint32_t aHb = sb;
        const uint32_t aLb = sb + GARR;
        const uint32_t bHb = sb + 2 * GARR;
        const uint32_t bLb = sb + 3 * GARR;

        const int a_row = (lane & 7) + ((lane >> 3) & 1) * 8;
        const int a_kb  = (lane >> 4) * 16;
        const int b_row = (lane & 7) + (lane >> 4) * 8;
        const int b_kb  = ((lane >> 3) & 1) * 16;

#pragma unroll
        for (int ks = 0; ks < 2; ks++) {
            const int kb = ks * 32;
            uint32_t ah[4][4], al[4][4], bh[2][4], bl[2][4];
#pragma unroll
            for (int mt = 0; mt < 4; mt++) {
                const uint32_t off = (wm * 64 + mt * 16 + a_row) * GROWB + kb + a_kb;
                ldmat4(ah[mt][0], ah[mt][1], ah[mt][2], ah[mt][3], aHb + off);
                ldmat4(al[mt][0], al[mt][1], al[mt][2], al[mt][3], aLb + off);
            }
#pragma unroll
            for (int np = 0; np < 2; np++) {
                const uint32_t off = (wn * 32 + np * 16 + b_row) * GROWB + kb + b_kb;
                ldmat4(bh[np][0], bh[np][1], bh[np][2], bh[np][3], bHb + off);
                ldmat4(bl[np][0], bl[np][1], bl[np][2], bl[np][3], bLb + off);
            }
#pragma unroll
            for (int mt = 0; mt < 4; mt++) {
#pragma unroll
                for (int nt = 0; nt < 4; nt++) {
                    uint32_t bfh[2] = { bh[nt >> 1][(nt & 1) * 2], bh[nt >> 1][(nt & 1) * 2 + 1] };
                    uint32_t bfl[2] = { bl[nt >> 1][(nt & 1) * 2], bl[nt >> 1][(nt & 1) * 2 + 1] };
                    mma_bf16(acc[mt][nt], ah[mt], bfh);
                    mma_bf16(acc[mt][nt], al[mt], bfh);
                    mma_bf16(acc[mt][nt], ah[mt], bfl);
                }
            }
        }
        __syncthreads();
    }

    const int g   = lane >> 2;
    const int t2  = (lane & 3) * 2;
#pragma unroll
    for (int mt = 0; mt < 4; mt++) {
        const int m = m0 + wm * 64 + mt * 16 + g;
#pragma unroll
        for (int nt = 0; nt < 4; nt++) {
            const int n = n0 + wn * 32 + nt * 8 + t2;
            const float b0 = bias[n], b1 = bias[n + 1];
            float2 v0 = make_float2(acc[mt][nt][0] + b0, acc[mt][nt][1] + b1);
            float2 v1 = make_float2(acc[mt][nt][2] + b0, acc[mt][nt][3] + b1);
            *(float2*)(C + (size_t)m * FH + n)       = v0;
            *(float2*)(C + (size_t)(m + 8) * FH + n) = v1;
        }
    }
}

// ---------------- LSTM scan (R12 base: 64 blocks/dir x 4 units, TC matmul) ----------------
#define HSROWB   528
#define OFF_HSH  0
#define OFF_HSL  67584
#define OFF_WSH  135168
#define OFF_WSL  143616
#define OFF_GST  152064
#define OFF_XST  160256
#define OFF_CST  168448
#define SCAN_SMEM_BYTES (168448 + 2048)

__device__ __forceinline__ float sigm(float x) { return 1.0f / (1.0f + expf(-x)); }

__global__ void __launch_bounds__(256, 1)
lstm_scan_kernel(const float* __restrict__ xWf, const float* __restrict__ xWb,
                 const float* __restrict__ WhhF, const float* __restrict__ WhhB,
                 float* __restrict__ lout,
                 __nv_bfloat16* __restrict__ sph, __nv_bfloat16* __restrict__ spl)
{
    extern __shared__ __align__(16) char smem[];
    float* gst = (float*)(smem + OFF_GST);
    float* xst = (float*)(smem + OFF_XST);
    float* cst = (float*)(smem + OFF_CST);

    const int tid   = threadIdx.x;
    const int dir   = blockIdx.x >> 6;
    const int slice = blockIdx.x & 63;
    const int j0    = slice << 2;

    const float* xW  = dir ? xWb  : xWf;
    const float* Whh = dir ? WhhB : WhhF;

    const uint32_t smb = smem_u32(smem);

    // convert Whh slice -> ws hi/lo (bf16, [16][264] rows)
    {
        const int l  = tid >> 4;
        const int ks = (tid & 15) * 16;
        const int grow = ((l >> 2) * HH) + j0 + (l & 3);
        const float* src = Whh + (size_t)grow * HH + ks;
        __nv_bfloat16* wh = (__nv_bfloat16*)(smem + OFF_WSH) + l * 264 + ks;
        __nv_bfloat16* wl = (__nv_bfloat16*)(smem + OFF_WSL) + l * 264 + ks;
#pragma unroll
        for (int i = 0; i < 16; i++) {
            float v = src[i];
            __nv_bfloat16 h = __float2bfloat16(v);
            wh[i] = h;
            wl[i] = __float2bfloat16(v - __bfloat162float(h));
        }
    }
    // zero hs (h0 = 0) and c state
    {
        float4* d4 = (float4*)(smem);
        float4 z = make_float4(0,0,0,0);
        for (int i = tid; i < (2 * 67584) / 16; i += 256) d4[i] = z;
        if (tid < 128) { cst[tid] = 0.f; cst[128+tid] = 0.f; cst[256+tid] = 0.f; cst[384+tid] = 0.f; }
    }
    __syncthreads();

    const int w = tid >> 5;
    const int lane = tid & 31;
    const int g  = lane >> 2;
    const int t2 = (lane & 3) * 2;
    const int a_row = (lane & 7) + ((lane >> 3) & 1) * 8;
    const int a_kb  = (lane >> 4) * 16;
    const int b_row = (lane & 7) + (lane >> 4) * 8;
    const int b_kb  = ((lane >> 3) & 1) * 16;

    for (int tt = 0; tt < SSQ; tt++) {
        const int t = dir ? (SSQ - 1 - tt) : tt;

        // load h(t-1) bf16 hi/lo into smem ([b][k] rows, 528B stride)
        if (tt > 0) {
            const int par = (tt - 1) & 1;
            const float4* srcH = (const float4*)(g_hh[par][dir]);
            const float4* srcL = (const float4*)(g_hl[par][dir]);
#pragma unroll
            for (int i = 0; i < 16; i++) {
                const int seg = tid + i * 256;
                const int row = seg >> 5;
                const int s   = seg & 31;
                *(float4*)(smem + OFF_HSH + row * HSROWB + s * 16) = srcH[seg];
                *(float4*)(smem + OFF_HSL + row * HSROWB + s * 16) = srcL[seg];
            }
        }
        // stage xW slice: xst[q*4+c][b]
#pragma unroll
        for (int half = 0; half < 2; half++) {
            const int p = tid + (half << 8);
            const int q = p >> 7;
            const int b = p & 127;
            float4 v = *(const float4*)&xW[((size_t)b * SSQ + t) * FH + (q << 8) + j0];
            xst[((q<<2)+0)*128 + b] = v.x;
            xst[((q<<2)+1)*128 + b] = v.y;
            xst[((q<<2)+2)*128 + b] = v.z;
            xst[((q<<2)+3)*128 + b] = v.w;
        }
        __syncthreads();

        // ---- tensor-core recurrent matmul: gst[16][128] = ws @ hs^T ----
        {
            float acc[2][4];
#pragma unroll
            for (int o = 0; o < 2; o++)
#pragma unroll
                for (int k = 0; k < 4; k++) acc[o][k] = 0.f;

#pragma unroll 4
            for (int ck = 0; ck < 16; ck++) {
                const int kb = ck * 32;
                uint32_t ah[4], al[4], bh[4], bl[4];
                ldmat4(ah[0], ah[1], ah[2], ah[3], smb + OFF_WSH + a_row * HSROWB + kb + a_kb);
                ldmat4(al[0], al[1], al[2], al[3], smb + OFF_WSL + a_row * HSROWB + kb + a_kb);
                ldmat4(bh[0], bh[1], bh[2], bh[3],
                       smb + OFF_HSH + (w * 16 + b_row) * HSROWB + kb + b_kb);
                ldmat4(bl[0], bl[1], bl[2], bl[3],
                       smb + OFF_HSL + (w * 16 + b_row) * HSROWB + kb + b_kb);
#pragma unroll
                for (int o = 0; o < 2; o++) {
                    uint32_t bfh[2] = { bh[o * 2], bh[o * 2 + 1] };
                    uint32_t bfl[2] = { bl[o * 2], bl[o * 2 + 1] };
                    mma_bf16(acc[o], ah, bfh);   // hi*hi
                    mma_bf16(acc[o], al, bfh);   // lo*hi
                    mma_bf16(acc[o], ah, bfl);   // hi*lo
                }
            }
#pragma unroll
            for (int o = 0; o < 2; o++) {
                const int n = w * 16 + o * 8 + t2;
                gst[g * 128 + n]           = acc[o][0];
                gst[g * 128 + n + 1]       = acc[o][1];
                gst[(g + 8) * 128 + n]     = acc[o][2];
                gst[(g + 8) * 128 + n + 1] = acc[o][3];
            }
            __syncthreads();
        }

        // ---- gate combine (packed 8B h stores) ----
        if (tid < 128) {
            const int b = tid;
            const int par = tt & 1;
            float hj[4];
            __nv_bfloat16 hbv[4], hlv[4];
#pragma unroll
            for (int jj = 0; jj < 4; jj++) {
                float gi = gst[(0  + jj)*128 + b] + xst[(0  + jj)*128 + b];
                float gf = gst[(4  + jj)*128 + b] + xst[(4  + jj)*128 + b];
                float gg = gst[(8  + jj)*128 + b] + xst[(8  + jj)*128 + b];
                float go = gst[(12 + jj)*128 + b] + xst[(12 + jj)*128 + b];
                float c  = cst[jj*128 + b];
                float si = sigm(gi), sf = sigm(gf), so = sigm(go);
                c = sf * c + si * tanhf(gg);
                float h = so * tanhf(c);
                cst[jj*128 + b] = c;
                hj[jj] = h;
                hbv[jj] = __float2bfloat16(h);
                hlv[jj] = __float2bfloat16(h - __bfloat162float(hbv[jj]));
            }
            *(uint2*)&g_hh[par][dir][b * HH + j0] = *(uint2*)hbv;
            *(uint2*)&g_hl[par][dir][b * HH + j0] = *(uint2*)hlv;
            if (lout)
                *(float4*)&lout[((size_t)b * SSQ + t) * (2*HH) + dir*HH + j0] =
                    make_float4(hj[0], hj[1], hj[2], hj[3]);
            if (sph) {
                const size_t off = ((size_t)b * SSQ + t) * (2*HH) + dir*HH + j0;
                __nv_bfloat16 sv[4], lv[4];
#pragma unroll
                for (int jj = 0; jj < 4; jj++) {
                    sv[jj] = __float2bfloat16(hj[jj]);
                    lv[jj] = __float2bfloat16(hj[jj] - __bfloat162float(sv[jj]));
                }
                *(uint2*)&sph[off] = *(uint2*)sv;
                *(uint2*)&spl[off] = *(uint2*)lv;
            }
        }
        __syncthreads();

        // ---- per-direction grid barrier: monotonic counter, tid0 only ----
        if (tt < SSQ - 1) {
            if (tid == 0) {
                const unsigned target = (unsigned)((tt + 1) * 64);
                unsigned old = atom_add_acqrel(&g_cnt[dir], 1u);
                if (old + 1u < target) {
                    while (ld_acq(&g_cnt[dir]) < target) __nanosleep(32);
                }
            }
            __syncthreads();
        }
    }
}

// ---------------- FC (T=9) ----------------
__global__ void __launch_bounds__(256)
fc_kernel(const float* __restrict__ l1, const float* __restrict__ fcw,
          const float* __restrict__ fcb, float* __restrict__ em)
{
    __shared__ float wsm[TT * 512];
    __shared__ float wb[TT];
    const int tid = threadIdx.x;
    for (int i = tid; i < TT*512; i += 256) wsm[i] = fcw[i];
    if (tid < TT) wb[tid] = fcb[tid];
    __syncthreads();

    const int warp = tid >> 5, lane = tid & 31;
    const int m = blockIdx.x * 8 + warp;
    const float* arow = l1 + (size_t)m * 512;
    float a[16];
#pragma unroll
    for (int c = 0; c < 16; c++) a[c] = arow[c*32 + lane];
    float* emrow = em + (size_t)m * TT;
#pragma unroll
    for (int j = 0; j < TT; j++) {
        float s = 0.f;
#pragma unroll
        for (int c = 0; c < 16; c++) s += a[c] * wsm[j*512 + c*32 + lane];
#pragma unroll
        for (int o = 16; o; o >>= 1) s += __shfl_xor_sync(0xffffffffu, s, o);
        if (lane == 0) emrow[j] = s + wb[j];
    }
}

// ---------------- CRF ----------------
__global__ void __launch_bounds__(1024)
crf_kernel(const int* __restrict__ x, const int* __restrict__ tags,
           const float* __restrict__ em, const float* __restrict__ start,
           const float* __restrict__ endv, const float* __restrict__ trans,
           float* __restrict__ partial)
{
    const int gw = (blockIdx.x * blockDim.x + threadIdx.x) >> 5;
    const int lane = threadIdx.x & 31;
    if (gw >= BB) return;
    const int b = gw;
    const float* emr = em + (size_t)b * SSQ * TT;
    const int* tg = tags + (size_t)b * SSQ;
    const int* xb = x + (size_t)b * SSQ;

    float nsum = 0.f; int mcount = 0;
    for (int s = lane; s < SSQ; s += 32) {
        const int m = (xb[s] != 0);
        mcount += m;
        if (s >= 1 && m) {
            const int tp = tg[s-1], tc = tg[s];
            nsum += trans[tp*TT + tc] + emr[(size_t)s*TT + tc];
        }
    }
#pragma unroll
    for (int o = 16; o; o >>= 1) {
        nsum   += __shfl_xor_sync(0xffffffffu, nsum, o);
        mcount += __shfl_xor_sync(0xffffffffu, mcount, o);
    }
    int last = mcount - 1; if (last < 0) last = 0;
    const int t0 = tg[0], tl = tg[last];
    const float num = nsum + start[t0] + emr[t0] + endv[tl];

    float tcol[TT];
#pragma unroll
    for (int i = 0; i < TT; i++) tcol[i] = 0.f;
    float alpha = -1e30f;
    if (lane < TT) {
#pragma unroll
        for (int i = 0; i < TT; i++) tcol[i] = trans[i*TT + lane];
        alpha = start[lane] + emr[lane];
    }
    for (int s = 1; s < SSQ; s++) {
        const float e = (lane < TT) ? emr[(size_t)s*TT + lane] : 0.f;
        const int m = (xb[s] != 0);
        float av[TT];
        float mx = -1e30f;
#pragma unroll
        for (int i = 0; i < TT; i++) {
            const float ai = __shfl_sync(0xffffffffu, alpha, i);
            av[i] = ai + tcol[i];
            mx = fmaxf(mx, av[i]);
        }
        float ssum = 0.f;
#pragma unroll
        for (int i = 0; i < TT; i++) ssum += expf(av[i] - mx);
        const float nxt = e + mx + logf(ssum);
        if (lane < TT && m) alpha = nxt;
    }
    float v = (lane < TT) ? alpha + endv[lane] : -1e30f;
    float mx = v;
#pragma unroll
    for (int o = 16; o; o >>= 1) mx = fmaxf(mx, __shfl_xor_sync(0xffffffffu, mx, o));
    float ex = (lane < TT) ? expf(v - mx) : 0.f;
#pragma unroll
    for (int o = 16; o; o >>= 1) ex += __shfl_xor_sync(0xffffffffu, ex, o);
    const float denom = mx + logf(ex);
    if (lane == 0) partial[b] = denom - num;
}

__global__ void reduce_mean_kernel(const float* __restrict__ partial, float* __restrict__ out)
{
    __shared__ float sm[BB];
    const int t = threadIdx.x;
    sm[t] = partial[t];
    __syncthreads();
    for (int o = 64; o; o >>= 1) { if (t < o) sm[t] += sm[t + o]; __syncthreads(); }
    if (t == 0) out[0] = sm[0] / (float)BB;
}

// ---------------- launch ----------------
extern "C" void kernel_launch(void* const* d_in, const int* in_sizes, int n_in,
                              void* d_out, int out_size)
{
    const int*   x     = (const int*)d_in[0];
    const int*   tags  = (const int*)d_in[1];
    const float* emb   = (const float*)d_in[2];
    const float* Wih0f = (const float*)d_in[3];
    const float* Whh0f = (const float*)d_in[4];
    const float* b0f   = (const float*)d_in[5];
    const float* Wih0b = (const float*)d_in[6];
    const float* Whh0b = (const float*)d_in[7];
    const float* b0b   = (const float*)d_in[8];
    const float* Wih1f = (const float*)d_in[9];
    const float* Whh1f = (const float*)d_in[10];
    const float* b1f   = (const float*)d_in[11];
    const float* Wih1b = (const float*)d_in[12];
    const float* Whh1b = (const float*)d_in[13];
    const float* b1b   = (const float*)d_in[14];
    const float* fcw   = (const float*)d_in[15];
    const float* fcb   = (const float*)d_in[16];
    const float* crf_s = (const float*)d_in[17];
    const float* crf_e = (const float*)d_in[18];
    const float* crf_t = (const float*)d_in[19];
    float* out = (float*)d_out;

    float *gA, *gB, *l1, *em, *part;
    cudaGetSymbolAddress((void**)&gA, g_gA);
    cudaGetSymbolAddress((void**)&gB, g_gB);
    cudaGetSymbolAddress((void**)&l1, g_l1);
    cudaGetSymbolAddress((void**)&em, g_em);
    cudaGetSymbolAddress((void**)&part, g_part);
    __nv_bfloat16 *embh, *embl, *Wh, *Wl, *l0h, *l0l;
    cudaGetSymbolAddress((void**)&embh, g_embh);
    cudaGetSymbolAddress((void**)&embl, g_embl);
    cudaGetSymbolAddress((void**)&Wh, g_Wh);
    cudaGetSymbolAddress((void**)&Wl, g_Wl);
    cudaGetSymbolAddress((void**)&l0h, g_l0h);
    cudaGetSymbolAddress((void**)&l0l, g_l0l);
    unsigned* cnt;
    cudaGetSymbolAddress((void**)&cnt, g_cnt);

    __nv_bfloat16* W0fh = Wh;                     __nv_bfloat16* W0fl = Wl;
    __nv_bfloat16* W0bh = Wh + (size_t)FH*512;    __nv_bfloat16* W0bl = Wl + (size_t)FH*512;
    __nv_bfloat16* W1fh = Wh + (size_t)FH*512*2;  __nv_bfloat16* W1fl = Wl + (size_t)FH*512*2;
    __nv_bfloat16* W1bh = Wh + (size_t)FH*512*3;  __nv_bfloat16* W1bl = Wl + (size_t)FH*512*3;

    cudaFuncSetAttribute(lstm_scan_kernel,
                         cudaFuncAttributeMaxDynamicSharedMemorySize, SCAN_SMEM_BYTES);
    cudaFuncSetAttribute(mma_gemm_kernel,
                         cudaFuncAttributeMaxDynamicSharedMemorySize, GEMM_SMEM);

    dim3 gg(MTOT/128, FH/128);

    // split conversions (weights + embedding; l0 split fused into scan)
    split_rows_kernel<<<VV, 256>>>(emb, embh, embl, EE, KP0);
    split_rows_kernel<<<FH, 256>>>(Wih0f, W0fh, W0fl, EE, KP0);
    split_rows_kernel<<<FH, 256>>>(Wih0b, W0bh, W0bl, EE, KP0);
    split_rows_kernel<<<FH, 256>>>(Wih1f, W1fh, W1fl, 512, 512);
    split_rows_kernel<<<FH, 256>>>(Wih1b, W1bh, W1bl, 512, 512);

    // layer 0
    mma_gemm_kernel<<<gg, 256, GEMM_SMEM>>>(embh, embl, W0fh, W0fl, b0f, gA, KP0, x);
    mma_gemm_kernel<<<gg, 256, GEMM_SMEM>>>(embh, embl, W0bh, W0bl, b0b, gB, KP0, x);
    cudaMemsetAsync(cnt, 0, 2 * sizeof(unsigned));
    lstm_scan_kernel<<<128, 256, SCAN_SMEM_BYTES>>>(gA, gB, Whh0f, Whh0b,
                                                    nullptr, l0h, l0l);
    // layer 1
    mma_gemm_kernel<<<gg, 256, GEMM_SMEM>>>(l0h, l0l, W1fh, W1fl, b1f, gA, 512, nullptr);
    mma_gemm_kernel<<<gg, 256, GEMM_SMEM>>>(l0h, l0l, W1bh, W1bl, b1b, gB, 512, nullptr);
    cudaMemsetAsync(cnt, 0, 2 * sizeof(unsigned));
    lstm_scan_kernel<<<128, 256, SCAN_SMEM_BYTES>>>(gA, gB, Whh1f, Whh1b,
                                                    l1, nullptr, nullptr);

    fc_kernel<<<MTOT/8, 256>>>(l1, fcw, fcb, em);
    crf_kernel<<<4, 1024>>>(x, tags, em, crf_s, crf_e, crf_t, part);
    reduce_mean_kernel<<<1, 128>>>(part, out);
}

// round 16
// speedup vs baseline: 1.5058x; 1.0019x over previous
#include <cuda_runtime.h>
#include <cuda_bf16.h>
#include <math.h>
#include <stdint.h>

#define BB   128
#define SSQ  512
#define EE   300
#define KP0  320
#define HH   256
#define FH   1024
#define TT   9
#define VV   50000
#define MTOT (BB*SSQ)

// ---------------- static device scratch ----------------
__device__ float g_gA[(size_t)MTOT * FH];
__device__ float g_gB[(size_t)MTOT * FH];
__device__ float g_l1[(size_t)MTOT * 2 * HH];
__device__ __nv_bfloat16 g_hh[2][2][BB * HH];   // h hi  [parity][dir][b][k]
__device__ __nv_bfloat16 g_hl[2][2][BB * HH];   // h lo
__device__ float g_em[(size_t)MTOT * TT];
__device__ float g_part[BB];
__device__ unsigned g_cnt[2];                    // monotonic barrier counters

// bf16 split buffers
__device__ __nv_bfloat16 g_embh[(size_t)VV * KP0];
__device__ __nv_bfloat16 g_embl[(size_t)VV * KP0];
__device__ __nv_bfloat16 g_Wh[4][(size_t)FH * 512];
__device__ __nv_bfloat16 g_Wl[4][(size_t)FH * 512];
__device__ __nv_bfloat16 g_l0h[(size_t)MTOT * 512];
__device__ __nv_bfloat16 g_l0l[(size_t)MTOT * 512];

// ---------------- helpers ----------------
__device__ __forceinline__ uint32_t smem_u32(const void* p) {
    uint32_t a;
    asm("{ .reg .u64 t; cvta.to.shared.u64 t, %1; cvt.u32.u64 %0, t; }" : "=r"(a) : "l"(p));
    return a;
}
__device__ __forceinline__ void cpa16(uint32_t dst, const void* src) {
    asm volatile("cp.async.cg.shared.global [%0], [%1], 16;" :: "r"(dst), "l"(src));
}
__device__ __forceinline__ void ldmat4(uint32_t& r0, uint32_t& r1, uint32_t& r2, uint32_t& r3,
                                       uint32_t addr) {
    asm volatile("ldmatrix.sync.aligned.m8n8.x4.shared.b16 {%0,%1,%2,%3}, [%4];"
                 : "=r"(r0), "=r"(r1), "=r"(r2), "=r"(r3) : "r"(addr));
}
__device__ __forceinline__ void mma_bf16(float* d, const uint32_t* a, const uint32_t* b) {
    asm volatile(
        "mma.sync.aligned.m16n8k16.row.col.f32.bf16.bf16.f32 "
        "{%0,%1,%2,%3}, {%4,%5,%6,%7}, {%8,%9}, {%0,%1,%2,%3};"
        : "+f"(d[0]), "+f"(d[1]), "+f"(d[2]), "+f"(d[3])
        : "r"(a[0]), "r"(a[1]), "r"(a[2]), "r"(a[3]), "r"(b[0]), "r"(b[1]));
}
__device__ __forceinline__ unsigned ld_acq(const unsigned* p) {
    unsigned v;
    asm volatile("ld.acquire.gpu.global.u32 %0, [%1];" : "=r"(v) : "l"(p) : "memory");
    return v;
}
__device__ __forceinline__ unsigned atom_add_acqrel(unsigned* p, unsigned v) {
    unsigned old;
    asm volatile("atom.acq_rel.gpu.global.add.u32 %0, [%1], %2;"
                 : "=r"(old) : "l"(p), "r"(v) : "memory");
    return old;
}

// ---------------- split conversion: fp32 -> bf16 hi/lo, padded ----------------
__global__ void __launch_bounds__(256)
split_rows_kernel(const float* __restrict__ src, __nv_bfloat16* __restrict__ hi,
                  __nv_bfloat16* __restrict__ lo, int K, int Kpad)
{
    const long r = blockIdx.x;
    const float* s = src + r * (long)K;
    __nv_bfloat16* hh = hi + r * (long)Kpad;
    __nv_bfloat16* ll = lo + r * (long)Kpad;
    for (int c = threadIdx.x; c < Kpad; c += blockDim.x) {
        float v = (c < K) ? s[c] : 0.f;
        __nv_bfloat16 h = __float2bfloat16(v);
        float res = v - __bfloat162float(h);
        hh[c] = h;
        ll[c] = __float2bfloat16(res);
    }
}

// ---------------- mma.sync bf16 split GEMM (proven R9) ----------------
#define GSTG      3
#define GROWB     80
#define GARR      (128 * GROWB)
#define GSTAGEB   (4 * GARR)
#define GEMM_SMEM (GSTG * GSTAGEB)

__global__ void __launch_bounds__(256)
mma_gemm_kernel(const __nv_bfloat16* __restrict__ Ahi, const __nv_bfloat16* __restrict__ Alo,
                const __nv_bfloat16* __restrict__ Whi, const __nv_bfloat16* __restrict__ Wlo,
                const float* __restrict__ bias, float* __restrict__ C,
                int Kpad, const int* __restrict__ rowidx)
{
    extern __shared__ __align__(16) char gsm[];
    __shared__ int xrow[128];

    const int tid = threadIdx.x;
    const int wid = tid >> 5;
    const int lane = tid & 31;
    const int m0 = blockIdx.x * 128;
    const int n0 = blockIdx.y * 128;
    const int wm = wid >> 2;
    const int wn = wid & 3;

    if (rowidx && tid < 128) xrow[tid] = rowidx[m0 + tid];
    __syncthreads();

    const uint32_t smb = smem_u32(gsm);
    const int nch = Kpad >> 5;

    const int lr_lo = tid >> 2;
    const int lks   = tid & 3;

    auto load_stage = [&](int c, int buf) {
        const uint32_t sb = smb + buf * GSTAGEB;
#pragma unroll
        for (int j = 0; j < 8; j++) {
            const int part = j >> 1;
            const int r    = (j & 1) * 64 + lr_lo;
            const uint32_t dst = sb + part * GARR + r * GROWB + lks * 16;
            const __nv_bfloat16* base;
            long row;
            if (part < 2) {
                base = (part == 0) ? Ahi : Alo;
                row  = rowidx ? xrow[r] : (m0 + r);
            } else {
                base = (part == 2) ? Whi : Wlo;
                row  = n0 + r;
            }
            cpa16(dst, base + row * (long)Kpad + c * 32 + lks * 8);
        }
        asm volatile("cp.async.commit_group;" ::: "memory");
    };

    float acc[4][4][4];
#pragma unroll
    for (int i = 0; i < 4; i++)
#pragma unroll
        for (int j = 0; j < 4; j++)
#pragma unroll
            for (int k = 0; k < 4; k++) acc[i][j][k] = 0.f;

    load_stage(0, 0);
    load_stage(1, 1);

    for (int c = 0; c < nch; c++) {
        if (c + 2 < nch) load_stage(c + 2, (c + 2) % GSTG);
        else asm volatile("cp.async.commit_group;" ::: "memory");
        asm volatile("cp.async.wait_group 2;" ::: "memory");
        __syncthreads();

        const uint32_t sb = smb + (c % GSTG) * GSTAGEB;
        const uint32_t aHb = sb;
        const uint32_t aLb = sb + GARR;
        const uint32_t bHb = sb + 2 * GARR;
        const uint32_t bLb = sb + 3 * GARR;

        const int a_row = (lane & 7) + ((lane >> 3) & 1) * 8;
        const int a_kb  = (lane >> 4) * 16;
        const int b_row = (lane & 7) + (lane >> 4) * 8;
        const int b_kb  = ((lane >> 3) & 1) * 16;

#pragma unroll
        for (int ks = 0; ks < 2; ks++) {
            const int kb = ks * 32;
            uint32_t ah[4][4], al[4][4], bh[2][4], bl[2][4];
#pragma unroll
            for (int mt = 0; mt < 4; mt++) {
                const uint32_t off = (wm * 64 + mt * 16 + a_row) * GROWB + kb + a_kb;
                ldmat4(ah[mt][0], ah[mt][1], ah[mt][2], ah[mt][3], aHb + off);
                ldmat4(al[mt][0], al[mt][1], al[mt][2], al[mt][3], aLb + off);
            }
#pragma unroll
            for (int np = 0; np < 2; np++) {
                const uint32_t off = (wn * 32 + np * 16 + b_row) * GROWB + kb + b_kb;
                ldmat4(bh[np][0], bh[np][1], bh[np][2], bh[np][3], bHb + off);
                ldmat4(bl[np][0], bl[np][1], bl[np][2], bl[np][3], bLb + off);
            }
#pragma unroll
            for (int mt = 0; mt < 4; mt++) {
#pragma unroll
                for (int nt = 0; nt < 4; nt++) {
                    uint32_t bfh[2] = { bh[nt >> 1][(nt & 1) * 2], bh[nt >> 1][(nt & 1) * 2 + 1] };
                    uint32_t bfl[2] = { bl[nt >> 1][(nt & 1) * 2], bl[nt >> 1][(nt & 1) * 2 + 1] };
                    mma_bf16(acc[mt][nt], ah[mt], bfh);
                    mma_bf16(acc[mt][nt], al[mt], bfh);
                    mma_bf16(acc[mt][nt], ah[mt], bfl);
                }
            }
        }
        __syncthreads();
    }

    const int g   = lane >> 2;
    const int t2  = (lane & 3) * 2;
#pragma unroll
    for (int mt = 0; mt < 4; mt++) {
        const int m = m0 + wm * 64 + mt * 16 + g;
#pragma unroll
        for (int nt = 0; nt < 4; nt++) {
            const int n = n0 + wn * 32 + nt * 8 + t2;
            const float b0 = bias[n], b1 = bias[n + 1];
            float2 v0 = make_float2(acc[mt][nt][0] + b0, acc[mt][nt][1] + b1);
            float2 v1 = make_float2(acc[mt][nt][2] + b0, acc[mt][nt][3] + b1);
            *(float2*)(C + (size_t)m * FH + n)       = v0;
            *(float2*)(C + (size_t)(m + 8) * FH + n) = v1;
        }
    }
}

// ---------------- LSTM scan (R14: 64 blocks/dir x 4 units, TC matmul, split h) ----------------
#define HSROWB   528
#define OFF_HSH  0
#define OFF_HSL  67584
#define OFF_WSH  135168
#define OFF_WSL  143616
#define OFF_GST  152064
#define OFF_XST  160256
#define OFF_CST  168448
#define SCAN_SMEM_BYTES (168448 + 2048)

__device__ __forceinline__ float sigm(float x) { return 1.0f / (1.0f + expf(-x)); }

__global__ void __launch_bounds__(256, 1)
lstm_scan_kernel(const float* __restrict__ xWf, const float* __restrict__ xWb,
                 const float* __restrict__ WhhF, const float* __restrict__ WhhB,
                 float* __restrict__ lout,
                 __nv_bfloat16* __restrict__ sph, __nv_bfloat16* __restrict__ spl)
{
    extern __shared__ __align__(16) char smem[];
    float* gst = (float*)(smem + OFF_GST);
    float* xst = (float*)(smem + OFF_XST);
    float* cst = (float*)(smem + OFF_CST);

    const int tid   = threadIdx.x;
    const int dir   = blockIdx.x >> 6;
    const int slice = blockIdx.x & 63;
    const int j0    = slice << 2;

    const float* xW  = dir ? xWb  : xWf;
    const float* Whh = dir ? WhhB : WhhF;

    const uint32_t smb = smem_u32(smem);

    // convert Whh slice -> ws hi/lo (bf16, [16][264] rows)
    {
        const int l  = tid >> 4;
        const int ks = (tid & 15) * 16;
        const int grow = ((l >> 2) * HH) + j0 + (l & 3);
        const float* src = Whh + (size_t)grow * HH + ks;
        __nv_bfloat16* wh = (__nv_bfloat16*)(smem + OFF_WSH) + l * 264 + ks;
        __nv_bfloat16* wl = (__nv_bfloat16*)(smem + OFF_WSL) + l * 264 + ks;
#pragma unroll
        for (int i = 0; i < 16; i++) {
            float v = src[i];
            __nv_bfloat16 h = __float2bfloat16(v);
            wh[i] = h;
            wl[i] = __float2bfloat16(v - __bfloat162float(h));
        }
    }
    // zero hs (h0 = 0) and c state
    {
        float4* d4 = (float4*)(smem);
        float4 z = make_float4(0,0,0,0);
        for (int i = tid; i < (2 * 67584) / 16; i += 256) d4[i] = z;
        if (tid < 128) { cst[tid] = 0.f; cst[128+tid] = 0.f; cst[256+tid] = 0.f; cst[384+tid] = 0.f; }
    }
    __syncthreads();

    const int w = tid >> 5;
    const int lane = tid & 31;
    const int g  = lane >> 2;
    const int t2 = (lane & 3) * 2;
    const int a_row = (lane & 7) + ((lane >> 3) & 1) * 8;
    const int a_kb  = (lane >> 4) * 16;
    const int b_row = (lane & 7) + (lane >> 4) * 8;
    const int b_kb  = ((lane >> 3) & 1) * 16;

    for (int tt = 0; tt < SSQ; tt++) {
        const int t = dir ? (SSQ - 1 - tt) : tt;

        // load h(t-1) bf16 hi/lo into smem ([b][k] rows, 528B stride)
        if (tt > 0) {
            const int par = (tt - 1) & 1;
            const float4* srcH = (const float4*)(g_hh[par][dir]);
            const float4* srcL = (const float4*)(g_hl[par][dir]);
#pragma unroll
            for (int i = 0; i < 16; i++) {
                const int seg = tid + i * 256;
                const int row = seg >> 5;
                const int s   = seg & 31;
                *(float4*)(smem + OFF_HSH + row * HSROWB + s * 16) = srcH[seg];
                *(float4*)(smem + OFF_HSL + row * HSROWB + s * 16) = srcL[seg];
            }
        }
        // stage xW slice: xst[q*4+c][b]
#pragma unroll
        for (int half = 0; half < 2; half++) {
            const int p = tid + (half << 8);
            const int q = p >> 7;
            const int b = p & 127;
            float4 v = *(const float4*)&xW[((size_t)b * SSQ + t) * FH + (q << 8) + j0];
            xst[((q<<2)+0)*128 + b] = v.x;
            xst[((q<<2)+1)*128 + b] = v.y;
            xst[((q<<2)+2)*128 + b] = v.z;
            xst[((q<<2)+3)*128 + b] = v.w;
        }
        __syncthreads();

        // ---- tensor-core recurrent matmul: gst[16][128] = ws @ hs^T ----
        {
            float acc[2][4];
#pragma unroll
            for (int o = 0; o < 2; o++)
#pragma unroll
                for (int k = 0; k < 4; k++) acc[o][k] = 0.f;

#pragma unroll 4
            for (int ck = 0; ck < 16; ck++) {
                const int kb = ck * 32;
                uint32_t ah[4], al[4], bh[4], bl[4];
                ldmat4(ah[0], ah[1], ah[2], ah[3], smb + OFF_WSH + a_row * HSROWB + kb + a_kb);
                ldmat4(al[0], al[1], al[2], al[3], smb + OFF_WSL + a_row * HSROWB + kb + a_kb);
                ldmat4(bh[0], bh[1], bh[2], bh[3],
                       smb + OFF_HSH + (w * 16 + b_row) * HSROWB + kb + b_kb);
                ldmat4(bl[0], bl[1], bl[2], bl[3],
                       smb + OFF_HSL + (w * 16 + b_row) * HSROWB + kb + b_kb);
#pragma unroll
                for (int o = 0; o < 2; o++) {
                    uint32_t bfh[2] = { bh[o * 2], bh[o * 2 + 1] };
                    uint32_t bfl[2] = { bl[o * 2], bl[o * 2 + 1] };
                    mma_bf16(acc[o], ah, bfh);   // hi*hi
                    mma_bf16(acc[o], al, bfh);   // lo*hi
                    mma_bf16(acc[o], ah, bfl);   // hi*lo
                }
            }
#pragma unroll
            for (int o = 0; o < 2; o++) {
                const int n = w * 16 + o * 8 + t2;
                gst[g * 128 + n]           = acc[o][0];
                gst[g * 128 + n + 1]       = acc[o][1];
                gst[(g + 8) * 128 + n]     = acc[o][2];
                gst[(g + 8) * 128 + n + 1] = acc[o][3];
            }
            __syncthreads();
        }

        // ---- gate combine (packed 8B h stores) ----
        if (tid < 128) {
            const int b = tid;
            const int par = tt & 1;
            float hj[4];
            __nv_bfloat16 hbv[4], hlv[4];
#pragma unroll
            for (int jj = 0; jj < 4; jj++) {
                float gi = gst[(0  + jj)*128 + b] + xst[(0  + jj)*128 + b];
                float gf = gst[(4  + jj)*128 + b] + xst[(4  + jj)*128 + b];
                float gg = gst[(8  + jj)*128 + b] + xst[(8  + jj)*128 + b];
                float go = gst[(12 + jj)*128 + b] + xst[(12 + jj)*128 + b];
                float c  = cst[jj*128 + b];
                float si = sigm(gi), sf = sigm(gf), so = sigm(go);
                c = sf * c + si * tanhf(gg);
                float h = so * tanhf(c);
                cst[jj*128 + b] = c;
                hj[jj] = h;
                hbv[jj] = __float2bfloat16(h);
                hlv[jj] = __float2bfloat16(h - __bfloat162float(hbv[jj]));
            }
            *(uint2*)&g_hh[par][dir][b * HH + j0] = *(uint2*)hbv;
            *(uint2*)&g_hl[par][dir][b * HH + j0] = *(uint2*)hlv;
            if (lout)
                *(float4*)&lout[((size_t)b * SSQ + t) * (2*HH) + dir*HH + j0] =
                    make_float4(hj[0], hj[1], hj[2], hj[3]);
            if (sph) {
                const size_t off = ((size_t)b * SSQ + t) * (2*HH) + dir*HH + j0;
                __nv_bfloat16 sv[4], lv[4];
#pragma unroll
                for (int jj = 0; jj < 4; jj++) {
                    sv[jj] = __float2bfloat16(hj[jj]);
                    lv[jj] = __float2bfloat16(hj[jj] - __bfloat162float(sv[jj]));
                }
                *(uint2*)&sph[off] = *(uint2*)sv;
                *(uint2*)&spl[off] = *(uint2*)lv;
            }
        }
        __syncthreads();

        // ---- per-direction grid barrier: monotonic counter, tid0 only ----
        if (tt < SSQ - 1) {
            if (tid == 0) {
                const unsigned target = (unsigned)((tt + 1) * 64);
                unsigned old = atom_add_acqrel(&g_cnt[dir], 1u);
                if (old + 1u < target) {
                    while (ld_acq(&g_cnt[dir]) < target) __nanosleep(16);
                }
            }
            __syncthreads();
        }
    }
}

// ---------------- FC (T=9) ----------------
__global__ void __launch_bounds__(256)
fc_kernel(const float* __restrict__ l1, const float* __restrict__ fcw,
          const float* __restrict__ fcb, float* __restrict__ em)
{
    __shared__ float wsm[TT * 512];
    __shared__ float wb[TT];
    const int tid = threadIdx.x;
    for (int i = tid; i < TT*512; i += 256) wsm[i] = fcw[i];
    if (tid < TT) wb[tid] = fcb[tid];
    __syncthreads();

    const int warp = tid >> 5, lane = tid & 31;
    const int m = blockIdx.x * 8 + warp;
    const float* arow = l1 + (size_t)m * 512;
    float a[16];
#pragma unroll
    for (int c = 0; c < 16; c++) a[c] = arow[c*32 + lane];
    float* emrow = em + (size_t)m * TT;
#pragma unroll
    for (int j = 0; j < TT; j++) {
        float s = 0.f;
#pragma unroll
        for (int c = 0; c < 16; c++) s += a[c] * wsm[j*512 + c*32 + lane];
#pragma unroll
        for (int o = 16; o; o >>= 1) s += __shfl_xor_sync(0xffffffffu, s, o);
        if (lane == 0) emrow[j] = s + wb[j];
    }
}

// ---------------- CRF ----------------
__global__ void __launch_bounds__(1024)
crf_kernel(const int* __restrict__ x, const int* __restrict__ tags,
           const float* __restrict__ em, const float* __restrict__ start,
           const float* __restrict__ endv, const float* __restrict__ trans,
           float* __restrict__ partial)
{
    const int gw = (blockIdx.x * blockDim.x + threadIdx.x) >> 5;
    const int lane = threadIdx.x & 31;
    if (gw >= BB) return;
    const int b = gw;
    const float* emr = em + (size_t)b * SSQ * TT;
    const int* tg = tags + (size_t)b * SSQ;
    const int* xb = x + (size_t)b * SSQ;

    float nsum = 0.f; int mcount = 0;
    for (int s = lane; s < SSQ; s += 32) {
        const int m = (xb[s] != 0);
        mcount += m;
        if (s >= 1 && m) {
            const int tp = tg[s-1], tc = tg[s];
            nsum += trans[tp*TT + tc] + emr[(size_t)s*TT + tc];
        }
    }
#pragma unroll
    for (int o = 16; o; o >>= 1) {
        nsum   += __shfl_xor_sync(0xffffffffu, nsum, o);
        mcount += __shfl_xor_sync(0xffffffffu, mcount, o);
    }
    int last = mcount - 1; if (last < 0) last = 0;
    const int t0 = tg[0], tl = tg[last];
    const float num = nsum + start[t0] + emr[t0] + endv[tl];

    float tcol[TT];
#pragma unroll
    for (int i = 0; i < TT; i++) tcol[i] = 0.f;
    float alpha = -1e30f;
    if (lane < TT) {
#pragma unroll
        for (int i = 0; i < TT; i++) tcol[i] = trans[i*TT + lane];
        alpha = start[lane] + emr[lane];
    }
    for (int s = 1; s < SSQ; s++) {
        const float e = (lane < TT) ? emr[(size_t)s*TT + lane] : 0.f;
        const int m = (xb[s] != 0);
        float av[TT];
        float mx = -1e30f;
#pragma unroll
        for (int i = 0; i < TT; i++) {
            const float ai = __shfl_sync(0xffffffffu, alpha, i);
            av[i] = ai + tcol[i];
            mx = fmaxf(mx, av[i]);
        }
        float ssum = 0.f;
#pragma unroll
        for (int i = 0; i < TT; i++) ssum += expf(av[i] - mx);
        const float nxt = e + mx + logf(ssum);
        if (lane < TT && m) alpha = nxt;
    }
    float v = (lane < TT) ? alpha + endv[lane] : -1e30f;
    float mx = v;
#pragma unroll
    for (int o = 16; o; o >>= 1) mx = fmaxf(mx, __shfl_xor_sync(0xffffffffu, mx, o));
    float ex = (lane < TT) ? expf(v - mx) : 0.f;
#pragma unroll
    for (int o = 16; o; o >>= 1) ex += __shfl_xor_sync(0xffffffffu, ex, o);
    const float denom = mx + logf(ex);
    if (lane == 0) partial[b] = denom - num;
}

__global__ void reduce_mean_kernel(const float* __restrict__ partial, float* __restrict__ out)
{
    __shared__ float sm[BB];
    const int t = threadIdx.x;
    sm[t] = partial[t];
    __syncthreads();
    for (int o = 64; o; o >>= 1) { if (t < o) sm[t] += sm[t + o]; __syncthreads(); }
    if (t == 0) out[0] = sm[0] / (float)BB;
}

// ---------------- launch ----------------
extern "C" void kernel_launch(void* const* d_in, const int* in_sizes, int n_in,
                              void* d_out, int out_size)
{
    const int*   x     = (const int*)d_in[0];
    const int*   tags  = (const int*)d_in[1];
    const float* emb   = (const float*)d_in[2];
    const float* Wih0f = (const float*)d_in[3];
    const float* Whh0f = (const float*)d_in[4];
    const float* b0f   = (const float*)d_in[5];
    const float* Wih0b = (const float*)d_in[6];
    const float* Whh0b = (const float*)d_in[7];
    const float* b0b   = (const float*)d_in[8];
    const float* Wih1f = (const float*)d_in[9];
    const float* Whh1f = (const float*)d_in[10];
    const float* b1f   = (const float*)d_in[11];
    const float* Wih1b = (const float*)d_in[12];
    const float* Whh1b = (const float*)d_in[13];
    const float* b1b   = (const float*)d_in[14];
    const float* fcw   = (const float*)d_in[15];
    const float* fcb   = (const float*)d_in[16];
    const float* crf_s = (const float*)d_in[17];
    const float* crf_e = (const float*)d_in[18];
    const float* crf_t = (const float*)d_in[19];
    float* out = (float*)d_out;

    float *gA, *gB, *l1, *em, *part;
    cudaGetSymbolAddress((void**)&gA, g_gA);
    cudaGetSymbolAddress((void**)&gB, g_gB);
    cudaGetSymbolAddress((void**)&l1, g_l1);
    cudaGetSymbolAddress((void**)&em, g_em);
    cudaGetSymbolAddress((void**)&part, g_part);
    __nv_bfloat16 *embh, *embl, *Wh, *Wl, *l0h, *l0l;
    cudaGetSymbolAddress((void**)&embh, g_embh);
    cudaGetSymbolAddress((void**)&embl, g_embl);
    cudaGetSymbolAddress((void**)&Wh, g_Wh);
    cudaGetSymbolAddress((void**)&Wl, g_Wl);
    cudaGetSymbolAddress((void**)&l0h, g_l0h);
    cudaGetSymbolAddress((void**)&l0l, g_l0l);
    unsigned* cnt;
    cudaGetSymbolAddress((void**)&cnt, g_cnt);

    __nv_bfloat16* W0fh = Wh;                     __nv_bfloat16* W0fl = Wl;
    __nv_bfloat16* W0bh = Wh + (size_t)FH*512;    __nv_bfloat16* W0bl = Wl + (size_t)FH*512;
    __nv_bfloat16* W1fh = Wh + (size_t)FH*512*2;  __nv_bfloat16* W1fl = Wl + (size_t)FH*512*2;
    __nv_bfloat16* W1bh = Wh + (size_t)FH*512*3;  __nv_bfloat16* W1bl = Wl + (size_t)FH*512*3;

    cudaFuncSetAttribute(lstm_scan_kernel,
                         cudaFuncAttributeMaxDynamicSharedMemorySize, SCAN_SMEM_BYTES);
    cudaFuncSetAttribute(mma_gemm_kernel,
                         cudaFuncAttributeMaxDynamicSharedMemorySize, GEMM_SMEM);

    dim3 gg(MTOT/128, FH/128);

    // split conversions (weights + embedding; l0 split fused into scan)
    split_rows_kernel<<<VV, 256>>>(emb, embh, embl, EE, KP0);
    split_rows_kernel<<<FH, 256>>>(Wih0f, W0fh, W0fl, EE, KP0);
    split_rows_kernel<<<FH, 256>>>(Wih0b, W0bh, W0bl, EE, KP0);
    split_rows_kernel<<<FH, 256>>>(Wih1f, W1fh, W1fl, 512, 512);
    split_rows_kernel<<<FH, 256>>>(Wih1b, W1bh, W1bl, 512, 512);

    // layer 0
    mma_gemm_kernel<<<gg, 256, GEMM_SMEM>>>(embh, embl, W0fh, W0fl, b0f, gA, KP0, x);
    mma_gemm_kernel<<<gg, 256, GEMM_SMEM>>>(embh, embl, W0bh, W0bl, b0b, gB, KP0, x);
    cudaMemsetAsync(cnt, 0, 2 * sizeof(unsigned));
    lstm_scan_kernel<<<128, 256, SCAN_SMEM_BYTES>>>(gA, gB, Whh0f, Whh0b,
                                                    nullptr, l0h, l0l);
    // layer 1
    mma_gemm_kernel<<<gg, 256, GEMM_SMEM>>>(l0h, l0l, W1fh, W1fl, b1f, gA, 512, nullptr);
    mma_gemm_kernel<<<gg, 256, GEMM_SMEM>>>(l0h, l0l, W1bh, W1bl, b1b, gB, 512, nullptr);
    cudaMemsetAsync(cnt, 0, 2 * sizeof(unsigned));
    lstm_scan_kernel<<<128, 256, SCAN_SMEM_BYTES>>>(gA, gB, Whh1f, Whh1b,
                                                    l1, nullptr, nullptr);

    fc_kernel<<<MTOT/8, 256>>>(l1, fcw, fcb, em);
    crf_kernel<<<4, 1024>>>(x, tags, em, crf_s, crf_e, crf_t, part);
    reduce_mean_kernel<<<1, 128>>>(part, out);
}